// round 14
// baseline (speedup 1.0000x reference)
#include <cuda_runtime.h>
#include <cuda_fp16.h>
#include <cuda_bf16.h>
#include <cstdint>

#define Mn 8192
#define Dn 128
#define DEG 32
#define SCALE 0.08838834764831845f
#define LOG2E 1.4426950408889634f
#define SC2   (SCALE * LOG2E)

// ---------------- device scratch (no allocations allowed) -------------------
__device__ __align__(16) float g_wg[Mn * Dn];
__device__ __align__(16) float g_local[Mn * Dn];
__device__ float g_ssrc[Mn];
__device__ float g_sdst[Mn];
__device__ int   g_idx64;
__device__ __align__(16) __half g_qh[Mn * Dn];     // [M, D]
__device__ __align__(16) __half g_kh[Mn * Dn];     // [M, D]
__device__ __align__(16) __half g_cth[Dn * Mn];    // [D, M] (transposed)
__device__ float g_qn[Mn];
__device__ unsigned int g_kmaxenc = 0;             // monotonic; idempotent across replays
__device__ __align__(16) float g_O[4][Mn * Dn];
__device__ float g_den[4][Mn];
__device__ int   g_cnt[32];                        // per-mtile completion counters

// ---------------- helpers ---------------------------------------------------
__device__ __forceinline__ uint32_t smem_to_u32(const void* p) {
    uint32_t a;
    asm("{ .reg .u64 t; cvta.to.shared.u64 t, %1; cvt.u32.u64 %0, t; }" : "=r"(a) : "l"(p));
    return a;
}
__device__ __forceinline__ void mma16816(float* d, const uint32_t* a, uint32_t b0, uint32_t b1) {
    asm volatile("mma.sync.aligned.m16n8k16.row.col.f32.f16.f16.f32 "
                 "{%0,%1,%2,%3}, {%4,%5,%6,%7}, {%8,%9}, {%0,%1,%2,%3};"
                 : "+f"(d[0]), "+f"(d[1]), "+f"(d[2]), "+f"(d[3])
                 : "r"(a[0]), "r"(a[1]), "r"(a[2]), "r"(a[3]), "r"(b0), "r"(b1));
}
__device__ __forceinline__ void mma16816bf(float* d, const uint32_t* a, uint32_t b0, uint32_t b1) {
    asm volatile("mma.sync.aligned.m16n8k16.row.col.f32.bf16.bf16.f32 "
                 "{%0,%1,%2,%3}, {%4,%5,%6,%7}, {%8,%9}, {%0,%1,%2,%3};"
                 : "+f"(d[0]), "+f"(d[1]), "+f"(d[2]), "+f"(d[3])
                 : "r"(a[0]), "r"(a[1]), "r"(a[2]), "r"(a[3]), "r"(b0), "r"(b1));
}
__device__ __forceinline__ uint32_t h2ex2(uint32_t x) {
    uint32_t r;
    asm("ex2.approx.f16x2 %0, %1;" : "=r"(r) : "r"(x));
    return r;
}
__device__ __forceinline__ uint32_t packbf2(float hi_x, float hi_y) {
    __nv_bfloat162 b = __floats2bfloat162_rn(hi_x, hi_y);
    return *(uint32_t*)&b;
}
#define LDSM4(r0, r1, r2, r3, addr) \
    asm volatile("ldmatrix.sync.aligned.m8n8.x4.shared.b16 {%0,%1,%2,%3}, [%4];" \
                 : "=r"(r0), "=r"(r1), "=r"(r2), "=r"(r3) : "r"(addr))
#define CP16(dst, src) asm volatile("cp.async.cg.shared.global [%0], [%1], 16;" :: "r"(dst), "l"(src))
#define CP_COMMIT() asm volatile("cp.async.commit_group;" ::: "memory")
#define CP_WAIT1()  asm volatile("cp.async.wait_group 1;"  ::: "memory")

#define CTH_OFF  17408
#define BUF_BYTES 35840

// ---------------------------------------------------------------------------
// proj via tensor cores (split-bf16, 3 MMA). grid (64, 4).
// Epilogue additionally produces: ssrc/sdst (which=0), qn (which=1),
// kmax (which=2), dtype detect + counter reset (block 0 of which=0).
// ---------------------------------------------------------------------------
__global__ __launch_bounds__(256, 1) void proj_mma_kernel(
    const float* __restrict__ z,
    const float* __restrict__ Wg, const float* __restrict__ Wq,
    const float* __restrict__ Wk, const float* __restrict__ Wc,
    const float* __restrict__ av, const int* __restrict__ ei32)
{
    extern __shared__ char smem[];             // Whi @0, Wlo @34816 (128 x 272B)
    int which = blockIdx.y;
    const float* W = (which == 0) ? Wg : (which == 1) ? Wq : (which == 2) ? Wk : Wc;
    int m0 = blockIdx.x * 128;
    int tid = threadIdx.x, wid = tid >> 5, lane = tid & 31;

    if (which == 0 && blockIdx.x == 0) {
        if (tid == 0) {
            int s = 0;
            for (int k = 16; k < 48; k++) s |= ei32[2 * k + 1];
            g_idx64 = (s == 0) ? 1 : 0;
        }
        if (tid < 32) g_cnt[tid] = 0;          // reset per replay (before flash)
    }

    for (int i = tid; i < Dn * Dn; i += 256) {
        int n = i >> 7, k = i & 127;
        float v = W[i];
        __nv_bfloat16 hi = __float2bfloat16(v);
        __nv_bfloat16 lo = __float2bfloat16(v - __bfloat162float(hi));
        *(__nv_bfloat16*)(smem + n * 272 + k * 2) = hi;
        *(__nv_bfloat16*)(smem + 34816 + n * 272 + k * 2) = lo;
    }

    int rbase = m0 + wid * 16 + (lane >> 2);
    int kcol = (lane & 3) * 2;
    uint32_t ah[8][4], al[8][4];
    #pragma unroll
    for (int g = 0; g < 8; g++) {
        int k0 = g * 16 + kcol;
        #pragma unroll
        for (int q = 0; q < 4; q++) {
            int r = rbase + ((q & 1) ? 8 : 0);
            int kk = k0 + ((q >> 1) ? 8 : 0);
            float2 v = *(const float2*)&z[r * Dn + kk];
            float hx = __bfloat162float(__float2bfloat16(v.x));
            float hy = __bfloat162float(__float2bfloat16(v.y));
            ah[g][q] = packbf2(hx, hy);
            al[g][q] = packbf2(v.x - hx, v.y - hy);
        }
    }
    __syncthreads();

    float acc[16][4];
    #pragma unroll
    for (int f = 0; f < 16; f++) acc[f][0] = acc[f][1] = acc[f][2] = acc[f][3] = 0.f;

    int boff = (lane >> 2) * 272 + kcol * 2;
    #pragma unroll
    for (int g = 0; g < 8; g++) {
        #pragma unroll
        for (int f = 0; f < 16; f++) {
            const char* p = smem + boff + f * 2176 + g * 32;
            uint32_t bh0 = *(const uint32_t*)p;
            uint32_t bh1 = *(const uint32_t*)(p + 16);
            uint32_t bl0 = *(const uint32_t*)(p + 34816);
            uint32_t bl1 = *(const uint32_t*)(p + 34816 + 16);
            mma16816bf(acc[f], ah[g], bh0, bh1);
            mma16816bf(acc[f], ah[g], bl0, bl1);
            mma16816bf(acc[f], al[g], bh0, bh1);
        }
    }

    // store + fused epilogue reductions
    #pragma unroll
    for (int f = 0; f < 16; f++) {
        int c0 = f * 8 + kcol;
        int r = rbase;
        if (which == 0) {
            *(float2*)&g_wg[r * Dn + c0]       = make_float2(acc[f][0], acc[f][1]);
            *(float2*)&g_wg[(r + 8) * Dn + c0] = make_float2(acc[f][2], acc[f][3]);
        } else if (which == 1) {
            *(__half2*)&g_qh[r * Dn + c0]       = __floats2half2_rn(acc[f][0], acc[f][1]);
            *(__half2*)&g_qh[(r + 8) * Dn + c0] = __floats2half2_rn(acc[f][2], acc[f][3]);
        } else if (which == 2) {
            *(__half2*)&g_kh[r * Dn + c0]       = __floats2half2_rn(acc[f][0], acc[f][1]);
            *(__half2*)&g_kh[(r + 8) * Dn + c0] = __floats2half2_rn(acc[f][2], acc[f][3]);
        } else {
            g_cth[(size_t)c0 * Mn + r]           = __float2half(acc[f][0]);
            g_cth[(size_t)(c0 + 1) * Mn + r]     = __float2half(acc[f][1]);
            g_cth[(size_t)c0 * Mn + r + 8]       = __float2half(acc[f][2]);
            g_cth[(size_t)(c0 + 1) * Mn + r + 8] = __float2half(acc[f][3]);
        }
    }

    if (which == 0) {
        float s0a = 0.f, s1a = 0.f, s0b = 0.f, s1b = 0.f;
        #pragma unroll
        for (int f = 0; f < 16; f++) {
            int c0 = f * 8 + kcol;
            s0a += acc[f][0] * av[c0] + acc[f][1] * av[c0 + 1];
            s1a += acc[f][0] * av[c0 + Dn] + acc[f][1] * av[c0 + Dn + 1];
            s0b += acc[f][2] * av[c0] + acc[f][3] * av[c0 + 1];
            s1b += acc[f][2] * av[c0 + Dn] + acc[f][3] * av[c0 + Dn + 1];
        }
        #pragma unroll
        for (int off = 1; off <= 2; off <<= 1) {
            s0a += __shfl_xor_sync(0xffffffffu, s0a, off);
            s1a += __shfl_xor_sync(0xffffffffu, s1a, off);
            s0b += __shfl_xor_sync(0xffffffffu, s0b, off);
            s1b += __shfl_xor_sync(0xffffffffu, s1b, off);
        }
        if ((lane & 3) == 0) {
            g_ssrc[rbase] = s0a;     g_sdst[rbase] = s1a;
            g_ssrc[rbase + 8] = s0b; g_sdst[rbase + 8] = s1b;
        }
    } else if (which == 1 || which == 2) {
        float na = 0.f, nb = 0.f;   // norms of the ROUNDED fp16 values
        #pragma unroll
        for (int f = 0; f < 16; f++) {
            #pragma unroll
            for (int q = 0; q < 4; q++) {
                float h = __half2float(__float2half_rn(acc[f][q]));
                if (q < 2) na += h * h; else nb += h * h;
            }
        }
        #pragma unroll
        for (int off = 1; off <= 2; off <<= 1) {
            na += __shfl_xor_sync(0xffffffffu, na, off);
            nb += __shfl_xor_sync(0xffffffffu, nb, off);
        }
        if ((lane & 3) == 0) {
            float ra = sqrtf(na), rb = sqrtf(nb);
            if (which == 1) {
                g_qn[rbase] = ra;
                g_qn[rbase + 8] = rb;
            } else {
                atomicMax(&g_kmaxenc, __float_as_uint(fmaxf(ra, rb)));
            }
        }
    }
}

// ---------------------------------------------------------------------------
// local aggregation, window-tiled (R12, proven)
// ---------------------------------------------------------------------------
#define NPB 16
#define WROWS 48
__global__ __launch_bounds__(256) void local_kernel(const void* __restrict__ ei)
{
    __shared__ float rows[WROWS * Dn];
    __shared__ float alpha_s[NPB * DEG];
    __shared__ int   dloc[NPB * DEG];
    int tid = threadIdx.x, wid = tid >> 5, lane = tid & 31;
    int n0 = blockIdx.x * NPB;
    int w0 = (n0 + 1) & (Mn - 1);

    for (int i = tid; i < WROWS * (Dn / 4); i += 256) {
        int r = i >> 5, c4 = (i & 31) * 4;
        int gr = (w0 + r) & (Mn - 1);
        *(float4*)&rows[r * Dn + c4] = *(const float4*)&g_wg[gr * Dn + c4];
    }

    #pragma unroll
    for (int p = 0; p < 2; p++) {
        int nl = p * 8 + wid;
        int node = n0 + nl;
        long long e = (long long)node * DEG + lane;
        int dj;
        if (g_idx64) dj = (int)((const long long*)ei)[(long long)Mn * DEG + e];
        else         dj = ((const int*)ei)[(long long)Mn * DEG + e];
        dj &= (Mn - 1);
        dloc[nl * DEG + lane] = dj;
        float s = g_ssrc[node] + g_sdst[dj];
        s = (s > 0.f) ? s : 0.01f * s;
        float mx = s;
        #pragma unroll
        for (int off = 16; off; off >>= 1) mx = fmaxf(mx, __shfl_xor_sync(0xffffffffu, mx, off));
        float e2 = __expf(s - mx);
        float sum = e2;
        #pragma unroll
        for (int off = 16; off; off >>= 1) sum += __shfl_xor_sync(0xffffffffu, sum, off);
        alpha_s[nl * DEG + lane] = e2 / sum;
    }
    __syncthreads();

    int nl = tid >> 4;
    int d0 = (tid & 15) * 8;
    float acc[8] = {0.f, 0.f, 0.f, 0.f, 0.f, 0.f, 0.f, 0.f};
    #pragma unroll 4
    for (int j = 0; j < DEG; j++) {
        float a = alpha_s[nl * DEG + j];
        int dj = dloc[nl * DEG + j];
        unsigned u = (unsigned)((dj - w0) & (Mn - 1));
        const float* src = (u < WROWS) ? &rows[u * Dn + d0] : &g_wg[dj * Dn + d0];
        float4 v0 = *(const float4*)src;
        float4 v1 = *(const float4*)(src + 4);
        acc[0] += a * v0.x; acc[1] += a * v0.y; acc[2] += a * v0.z; acc[3] += a * v0.w;
        acc[4] += a * v1.x; acc[5] += a * v1.y; acc[6] += a * v1.z; acc[7] += a * v1.w;
    }
    float* dst = &g_local[(n0 + nl) * Dn + d0];
    *(float4*)dst       = make_float4(acc[0], acc[1], acc[2], acc[3]);
    *(float4*)(dst + 4) = make_float4(acc[4], acc[5], acc[6], acc[7]);
}

// ---------------------------------------------------------------------------
// flash attention (R12 config: BM=256, 1 CTA/SM) + fused final epilogue:
// the last-finishing CTA of each m-tile computes out = leaky(local+O/den+z)
// reading all four K-split arrays in fixed order (deterministic output).
// ---------------------------------------------------------------------------
__device__ __forceinline__ void load_tiles(uint32_t sbuf, int j0, int tid)
{
    #pragma unroll
    for (int l = 0; l < 4; l++) {
        int c = tid + 256 * l;
        int row = c >> 4, ch = c & 15;
        const char* s1 = (const char*)(g_kh + (size_t)(j0 + row) * Dn) + ch * 16;
        CP16(sbuf + row * 272 + ch * 16, s1);
    }
    #pragma unroll
    for (int l = 0; l < 4; l++) {
        int c = tid + 256 * l;
        int d = c >> 3, ch = c & 7;
        const char* s1 = (const char*)(g_cth + (size_t)d * Mn + j0) + ch * 16;
        CP16(sbuf + CTH_OFF + d * 144 + ch * 16, s1);
    }
}

__global__ __launch_bounds__(256, 1) void flash_mma_kernel(const float* __restrict__ z,
                                                           float* __restrict__ out)
{
    extern __shared__ char smem[];
    uint32_t sb = smem_to_u32(smem);
    int tid = threadIdx.x, wid = tid >> 5, lane = tid & 31;
    int mt = blockIdx.x >> 2, ks = blockIdx.x & 3;
    int m0 = mt * 256, jbase = ks * 2048;
    int rbase = m0 + wid * 32 + (lane >> 2);
    int kcol = (lane & 3) * 2;

    uint32_t kaddr = (uint32_t)((lane & 7) * 272 + (lane >> 3) * 16);
    uint32_t caddr = (uint32_t)(CTH_OFF + ((lane & 7) + (lane >> 4) * 8) * 144 + ((lane >> 3) & 1) * 16);

    uint32_t qf[2][8][4];
    #pragma unroll
    for (int mi = 0; mi < 2; mi++) {
        int r = rbase + mi * 16;
        #pragma unroll
        for (int g = 0; g < 8; g++) {
            int k0 = g * 16 + kcol;
            qf[mi][g][0] = *(const uint32_t*)&g_qh[r * Dn + k0];
            qf[mi][g][1] = *(const uint32_t*)&g_qh[(r + 8) * Dn + k0];
            qf[mi][g][2] = *(const uint32_t*)&g_qh[r * Dn + k0 + 8];
            qf[mi][g][3] = *(const uint32_t*)&g_qh[(r + 8) * Dn + k0 + 8];
        }
    }
    float kmax = __uint_as_float(g_kmaxenc);
    float ce[4];
    #pragma unroll
    for (int rr = 0; rr < 4; rr++)
        ce[rr] = 14.0f - g_qn[rbase + ((rr & 1) ? 8 : 0) + ((rr >> 1) ? 16 : 0)] * kmax * SC2;

    float Oa[2][16][4];
    #pragma unroll
    for (int mi = 0; mi < 2; mi++)
        #pragma unroll
        for (int f = 0; f < 16; f++)
            Oa[mi][f][0] = Oa[mi][f][1] = Oa[mi][f][2] = Oa[mi][f][3] = 0.f;
    __half2 hs[4];
    hs[0] = hs[1] = hs[2] = hs[3] = __floats2half2_rn(0.f, 0.f);
    float dn[4] = {0.f, 0.f, 0.f, 0.f};

    load_tiles(sb, jbase, tid);                  CP_COMMIT();
    load_tiles(sb + BUF_BYTES, jbase + 64, tid); CP_COMMIT();

    for (int it = 0; it < 32; it++) {
        CP_WAIT1();
        __syncthreads();
        if (it + 2 < 32) load_tiles(sb + ((it + 2) % 3) * BUF_BYTES, jbase + (it + 2) * 64, tid);
        CP_COMMIT();

        uint32_t kb = sb + (it % 3) * BUF_BYTES + kaddr;
        uint32_t cb = sb + (it % 3) * BUF_BYTES + caddr;

        #pragma unroll
        for (int gp = 0; gp < 4; gp++) {
            uint32_t Ah0[4], Ah1[4];
            #pragma unroll
            for (int tt = 0; tt < 2; tt++) {
                int t = gp * 2 + tt;
                float S0a[4] = {0.f, 0.f, 0.f, 0.f}, S0b[4] = {0.f, 0.f, 0.f, 0.f};
                float S1a[4] = {0.f, 0.f, 0.f, 0.f}, S1b[4] = {0.f, 0.f, 0.f, 0.f};
                #pragma unroll
                for (int g2 = 0; g2 < 8; g2 += 2) {
                    uint32_t r0, r1, r2, r3;
                    LDSM4(r0, r1, r2, r3, kb + t * 2176 + g2 * 32);
                    mma16816(S0a, qf[0][g2],     r0, r1);
                    mma16816(S1a, qf[1][g2],     r0, r1);
                    mma16816(S0b, qf[0][g2 + 1], r2, r3);
                    mma16816(S1b, qf[1][g2 + 1], r2, r3);
                }
                __half2 x01 = __floats2half2_rn(fmaf(S0a[0] + S0b[0], SC2, ce[0]),
                                                fmaf(S0a[1] + S0b[1], SC2, ce[0]));
                __half2 x23 = __floats2half2_rn(fmaf(S0a[2] + S0b[2], SC2, ce[1]),
                                                fmaf(S0a[3] + S0b[3], SC2, ce[1]));
                __half2 y01 = __floats2half2_rn(fmaf(S1a[0] + S1b[0], SC2, ce[2]),
                                                fmaf(S1a[1] + S1b[1], SC2, ce[2]));
                __half2 y23 = __floats2half2_rn(fmaf(S1a[2] + S1b[2], SC2, ce[3]),
                                                fmaf(S1a[3] + S1b[3], SC2, ce[3]));
                uint32_t e01 = h2ex2(*(uint32_t*)&x01);
                uint32_t e23 = h2ex2(*(uint32_t*)&x23);
                uint32_t f01 = h2ex2(*(uint32_t*)&y01);
                uint32_t f23 = h2ex2(*(uint32_t*)&y23);
                hs[0] = __hadd2(hs[0], *(__half2*)&e01);
                hs[1] = __hadd2(hs[1], *(__half2*)&e23);
                hs[2] = __hadd2(hs[2], *(__half2*)&f01);
                hs[3] = __hadd2(hs[3], *(__half2*)&f23);
                Ah0[tt * 2 + 0] = e01;
                Ah0[tt * 2 + 1] = e23;
                Ah1[tt * 2 + 0] = f01;
                Ah1[tt * 2 + 1] = f23;
            }
            #pragma unroll
            for (int f2 = 0; f2 < 8; f2++) {
                uint32_t r0, r1, r2, r3;
                LDSM4(r0, r1, r2, r3, cb + f2 * 2304 + gp * 32);
                mma16816(Oa[0][2 * f2],     Ah0, r0, r1);
                mma16816(Oa[1][2 * f2],     Ah1, r0, r1);
                mma16816(Oa[0][2 * f2 + 1], Ah0, r2, r3);
                mma16816(Oa[1][2 * f2 + 1], Ah1, r2, r3);
            }
        }
        #pragma unroll
        for (int rr = 0; rr < 4; rr++) {
            float2 f2 = __half22float2(hs[rr]);
            dn[rr] += f2.x + f2.y;
            hs[rr] = __floats2half2_rn(0.f, 0.f);
        }
    }

    #pragma unroll
    for (int rr = 0; rr < 4; rr++) {
        dn[rr] += __shfl_xor_sync(0xffffffffu, dn[rr], 1);
        dn[rr] += __shfl_xor_sync(0xffffffffu, dn[rr], 2);
    }
    if ((lane & 3) == 0) {
        g_den[ks][rbase]      = dn[0];
        g_den[ks][rbase + 8]  = dn[1];
        g_den[ks][rbase + 16] = dn[2];
        g_den[ks][rbase + 24] = dn[3];
    }

    float* Op = g_O[ks];
    #pragma unroll
    for (int mi = 0; mi < 2; mi++) {
        int r = rbase + mi * 16;
        #pragma unroll
        for (int f = 0; f < 16; f++) {
            int c0 = f * 8 + kcol;
            *(float2*)&Op[r * Dn + c0]       = make_float2(Oa[mi][f][0], Oa[mi][f][1]);
            *(float2*)&Op[(r + 8) * Dn + c0] = make_float2(Oa[mi][f][2], Oa[mi][f][3]);
        }
    }

    // ---- last-CTA-per-mtile fused final epilogue ----
    __threadfence();
    __syncthreads();
    __shared__ int lastf;
    if (tid == 0) lastf = (atomicAdd(&g_cnt[mt], 1) == 3) ? 1 : 0;
    __syncthreads();
    if (!lastf) return;
    __threadfence();   // acquire: other CTAs' O/den writes now visible

    float invr[4];
    #pragma unroll
    for (int rr = 0; rr < 4; rr++) {
        int r = rbase + ((rr & 1) ? 8 : 0) + ((rr >> 1) ? 16 : 0);
        invr[rr] = 1.0f / (g_den[0][r] + g_den[1][r] + g_den[2][r] + g_den[3][r]);
    }
    #pragma unroll
    for (int mi = 0; mi < 2; mi++) {
        #pragma unroll
        for (int half = 0; half < 2; half++) {
            int r = rbase + mi * 16 + half * 8;
            float inv = invr[mi * 2 + half];
            #pragma unroll
            for (int f = 0; f < 16; f++) {
                int c0 = f * 8 + kcol;
                size_t o = (size_t)r * Dn + c0;
                float2 s = make_float2(0.f, 0.f);
                #pragma unroll
                for (int k2 = 0; k2 < 4; k2++) {          // fixed order: deterministic
                    float2 t = *(const float2*)&g_O[k2][o];
                    s.x += t.x; s.y += t.y;
                }
                float2 lc = *(const float2*)&g_local[o];
                float2 zz = *(const float2*)&z[o];
                float v0 = lc.x + s.x * inv + zz.x;
                float v1 = lc.y + s.y * inv + zz.y;
                v0 = (v0 > 0.f) ? v0 : 0.01f * v0;
                v1 = (v1 > 0.f) ? v1 : 0.01f * v1;
                *(float2*)&out[o] = make_float2(v0, v1);
            }
        }
    }
}

// ---------------------------------------------------------------------------
extern "C" void kernel_launch(void* const* d_in, const int* in_sizes, int n_in,
                              void* d_out, int out_size)
{
    const float* z  = (const float*)d_in[0];
    const void*  ei = d_in[1];
    const float* Wg = (const float*)d_in[2];
    const float* Wc = (const float*)d_in[3];
    const float* Wq = (const float*)d_in[4];
    const float* Wk = (const float*)d_in[5];
    const float* a  = (const float*)d_in[6];
    float* out = (float*)d_out;

    cudaFuncSetAttribute((const void*)flash_mma_kernel,
                         cudaFuncAttributeMaxDynamicSharedMemorySize, 3 * BUF_BYTES);
    cudaFuncSetAttribute((const void*)proj_mma_kernel,
                         cudaFuncAttributeMaxDynamicSharedMemorySize, 69632);

    proj_mma_kernel<<<dim3(64, 4), 256, 69632>>>(z, Wg, Wq, Wk, Wc, a, (const int*)ei);
    local_kernel<<<Mn / NPB, 256>>>(ei);
    flash_mma_kernel<<<128, 256, 3 * BUF_BYTES>>>(z, out);
}

// round 15
// speedup vs baseline: 1.1345x; 1.1345x over previous
#include <cuda_runtime.h>
#include <cuda_fp16.h>
#include <cuda_bf16.h>
#include <cstdint>

#define Mn 8192
#define Dn 128
#define DEG 32
#define SCALE 0.08838834764831845f
#define LOG2E 1.4426950408889634f
#define SC2   (SCALE * LOG2E)

// ---------------- device scratch (no allocations allowed) -------------------
__device__ __align__(16) float g_wg[Mn * Dn];
__device__ __align__(16) float g_local[Mn * Dn];
__device__ float g_ssrc[Mn];
__device__ float g_sdst[Mn];
__device__ int   g_idx64;
__device__ __align__(16) __half g_qh[Mn * Dn];     // [M, D]
__device__ __align__(16) __half g_kh[Mn * Dn];     // [M, D]
__device__ __align__(16) __half g_cth[Dn * Mn];    // [D, M] (transposed)
__device__ float g_qn[Mn];
__device__ unsigned int g_kmaxenc = 0;             // monotonic; idempotent across replays
__device__ __align__(16) float g_O[4][Mn * Dn];
__device__ float g_den[4][Mn];
// pre-converted W planes, in the exact smem image layout:
//   hi at n*272 + k*2, lo at 34816 + n*272 + k*2   (69632 B per weight)
__device__ __align__(16) char g_wplanes[4][69632];

// ---------------- helpers ---------------------------------------------------
__device__ __forceinline__ uint32_t smem_to_u32(const void* p) {
    uint32_t a;
    asm("{ .reg .u64 t; cvta.to.shared.u64 t, %1; cvt.u32.u64 %0, t; }" : "=r"(a) : "l"(p));
    return a;
}
__device__ __forceinline__ void mma16816(float* d, const uint32_t* a, uint32_t b0, uint32_t b1) {
    asm volatile("mma.sync.aligned.m16n8k16.row.col.f32.f16.f16.f32 "
                 "{%0,%1,%2,%3}, {%4,%5,%6,%7}, {%8,%9}, {%0,%1,%2,%3};"
                 : "+f"(d[0]), "+f"(d[1]), "+f"(d[2]), "+f"(d[3])
                 : "r"(a[0]), "r"(a[1]), "r"(a[2]), "r"(a[3]), "r"(b0), "r"(b1));
}
__device__ __forceinline__ void mma16816bf(float* d, const uint32_t* a, uint32_t b0, uint32_t b1) {
    asm volatile("mma.sync.aligned.m16n8k16.row.col.f32.bf16.bf16.f32 "
                 "{%0,%1,%2,%3}, {%4,%5,%6,%7}, {%8,%9}, {%0,%1,%2,%3};"
                 : "+f"(d[0]), "+f"(d[1]), "+f"(d[2]), "+f"(d[3])
                 : "r"(a[0]), "r"(a[1]), "r"(a[2]), "r"(a[3]), "r"(b0), "r"(b1));
}
__device__ __forceinline__ uint32_t h2ex2(uint32_t x) {
    uint32_t r;
    asm("ex2.approx.f16x2 %0, %1;" : "=r"(r) : "r"(x));
    return r;
}
__device__ __forceinline__ uint32_t packbf2(float hi_x, float hi_y) {
    __nv_bfloat162 b = __floats2bfloat162_rn(hi_x, hi_y);
    return *(uint32_t*)&b;
}
#define LDSM4(r0, r1, r2, r3, addr) \
    asm volatile("ldmatrix.sync.aligned.m8n8.x4.shared.b16 {%0,%1,%2,%3}, [%4];" \
                 : "=r"(r0), "=r"(r1), "=r"(r2), "=r"(r3) : "r"(addr))
#define CP16(dst, src) asm volatile("cp.async.cg.shared.global [%0], [%1], 16;" :: "r"(dst), "l"(src))
#define CP_COMMIT() asm volatile("cp.async.commit_group;" ::: "memory")
#define CP_WAIT1()  asm volatile("cp.async.wait_group 1;"  ::: "memory")
#define CP_WAIT0()  asm volatile("cp.async.wait_group 0;"  ::: "memory")

#define CTH_OFF  17408
#define BUF_BYTES 35840

// ---------------------------------------------------------------------------
// W pre-conversion: fp32 -> split-bf16 planes in smem-image layout. grid 4.
// ---------------------------------------------------------------------------
__global__ __launch_bounds__(256) void convert_w_kernel(
    const float* __restrict__ Wg, const float* __restrict__ Wq,
    const float* __restrict__ Wk, const float* __restrict__ Wc)
{
    int b = blockIdx.x;
    const float* W = (b == 0) ? Wg : (b == 1) ? Wq : (b == 2) ? Wk : Wc;
    char* dst = g_wplanes[b];
    for (int i = threadIdx.x; i < Dn * Dn / 2; i += 256) {
        int n = i >> 6, k2 = (i & 63) * 2;
        float2 v = *(const float2*)&W[n * Dn + k2];
        float hx = __bfloat162float(__float2bfloat16(v.x));
        float hy = __bfloat162float(__float2bfloat16(v.y));
        *(uint32_t*)(dst + n * 272 + k2 * 2)         = packbf2(hx, hy);
        *(uint32_t*)(dst + 34816 + n * 272 + k2 * 2) = packbf2(v.x - hx, v.y - hy);
    }
}

// ---------------------------------------------------------------------------
// proj via tensor cores (split-bf16, 3 MMA). grid (64, 4).
// W planes arrive by cp.async (pre-converted); epilogue fuses scores/norms.
// ---------------------------------------------------------------------------
__global__ __launch_bounds__(256, 1) void proj_mma_kernel(
    const float* __restrict__ z,
    const float* __restrict__ av, const int* __restrict__ ei32)
{
    extern __shared__ char smem[];             // 69632 B: Whi @0, Wlo @34816
    uint32_t sb = smem_to_u32(smem);
    int which = blockIdx.y;
    int m0 = blockIdx.x * 128;
    int tid = threadIdx.x, wid = tid >> 5, lane = tid & 31;

    // async-copy the W image (overlaps the z fragment LDGs below)
    {
        const char* src = g_wplanes[which];
        #pragma unroll
        for (int l = 0; l < 17; l++) {
            int off = (l * 256 + tid) * 16;    // 17*256*16 = 69632
            CP16(sb + off, src + off);
        }
        CP_COMMIT();
    }

    if (which == 0 && blockIdx.x == 0 && tid == 0) {
        int s = 0;
        for (int k = 16; k < 48; k++) s |= ei32[2 * k + 1];
        g_idx64 = (s == 0) ? 1 : 0;
    }

    int rbase = m0 + wid * 16 + (lane >> 2);
    int kcol = (lane & 3) * 2;
    uint32_t ah[8][4], al[8][4];
    #pragma unroll
    for (int g = 0; g < 8; g++) {
        int k0 = g * 16 + kcol;
        #pragma unroll
        for (int q = 0; q < 4; q++) {
            int r = rbase + ((q & 1) ? 8 : 0);
            int kk = k0 + ((q >> 1) ? 8 : 0);
            float2 v = *(const float2*)&z[r * Dn + kk];
            float hx = __bfloat162float(__float2bfloat16(v.x));
            float hy = __bfloat162float(__float2bfloat16(v.y));
            ah[g][q] = packbf2(hx, hy);
            al[g][q] = packbf2(v.x - hx, v.y - hy);
        }
    }
    CP_WAIT0();
    __syncthreads();

    float acc[16][4];
    #pragma unroll
    for (int f = 0; f < 16; f++) acc[f][0] = acc[f][1] = acc[f][2] = acc[f][3] = 0.f;

    int boff = (lane >> 2) * 272 + kcol * 2;
    #pragma unroll
    for (int g = 0; g < 8; g++) {
        #pragma unroll
        for (int f = 0; f < 16; f++) {
            const char* p = smem + boff + f * 2176 + g * 32;
            uint32_t bh0 = *(const uint32_t*)p;
            uint32_t bh1 = *(const uint32_t*)(p + 16);
            uint32_t bl0 = *(const uint32_t*)(p + 34816);
            uint32_t bl1 = *(const uint32_t*)(p + 34816 + 16);
            mma16816bf(acc[f], ah[g], bh0, bh1);
            mma16816bf(acc[f], ah[g], bl0, bl1);
            mma16816bf(acc[f], al[g], bh0, bh1);
        }
    }

    // store + fused epilogue reductions
    #pragma unroll
    for (int f = 0; f < 16; f++) {
        int c0 = f * 8 + kcol;
        int r = rbase;
        if (which == 0) {
            *(float2*)&g_wg[r * Dn + c0]       = make_float2(acc[f][0], acc[f][1]);
            *(float2*)&g_wg[(r + 8) * Dn + c0] = make_float2(acc[f][2], acc[f][3]);
        } else if (which == 1) {
            *(__half2*)&g_qh[r * Dn + c0]       = __floats2half2_rn(acc[f][0], acc[f][1]);
            *(__half2*)&g_qh[(r + 8) * Dn + c0] = __floats2half2_rn(acc[f][2], acc[f][3]);
        } else if (which == 2) {
            *(__half2*)&g_kh[r * Dn + c0]       = __floats2half2_rn(acc[f][0], acc[f][1]);
            *(__half2*)&g_kh[(r + 8) * Dn + c0] = __floats2half2_rn(acc[f][2], acc[f][3]);
        } else {
            g_cth[(size_t)c0 * Mn + r]           = __float2half(acc[f][0]);
            g_cth[(size_t)(c0 + 1) * Mn + r]     = __float2half(acc[f][1]);
            g_cth[(size_t)c0 * Mn + r + 8]       = __float2half(acc[f][2]);
            g_cth[(size_t)(c0 + 1) * Mn + r + 8] = __float2half(acc[f][3]);
        }
    }

    if (which == 0) {
        float s0a = 0.f, s1a = 0.f, s0b = 0.f, s1b = 0.f;
        #pragma unroll
        for (int f = 0; f < 16; f++) {
            int c0 = f * 8 + kcol;
            s0a += acc[f][0] * av[c0] + acc[f][1] * av[c0 + 1];
            s1a += acc[f][0] * av[c0 + Dn] + acc[f][1] * av[c0 + Dn + 1];
            s0b += acc[f][2] * av[c0] + acc[f][3] * av[c0 + 1];
            s1b += acc[f][2] * av[c0 + Dn] + acc[f][3] * av[c0 + Dn + 1];
        }
        #pragma unroll
        for (int off = 1; off <= 2; off <<= 1) {
            s0a += __shfl_xor_sync(0xffffffffu, s0a, off);
            s1a += __shfl_xor_sync(0xffffffffu, s1a, off);
            s0b += __shfl_xor_sync(0xffffffffu, s0b, off);
            s1b += __shfl_xor_sync(0xffffffffu, s1b, off);
        }
        if ((lane & 3) == 0) {
            g_ssrc[rbase] = s0a;     g_sdst[rbase] = s1a;
            g_ssrc[rbase + 8] = s0b; g_sdst[rbase + 8] = s1b;
        }
    } else if (which == 1 || which == 2) {
        float na = 0.f, nb = 0.f;   // norms of the ROUNDED fp16 values
        #pragma unroll
        for (int f = 0; f < 16; f++) {
            #pragma unroll
            for (int q = 0; q < 4; q++) {
                float h = __half2float(__float2half_rn(acc[f][q]));
                if (q < 2) na += h * h; else nb += h * h;
            }
        }
        #pragma unroll
        for (int off = 1; off <= 2; off <<= 1) {
            na += __shfl_xor_sync(0xffffffffu, na, off);
            nb += __shfl_xor_sync(0xffffffffu, nb, off);
        }
        if ((lane & 3) == 0) {
            float ra = sqrtf(na), rb = sqrtf(nb);
            if (which == 1) {
                g_qn[rbase] = ra;
                g_qn[rbase + 8] = rb;
            } else {
                atomicMax(&g_kmaxenc, __float_as_uint(fmaxf(ra, rb)));
            }
        }
    }
}

// ---------------------------------------------------------------------------
// local aggregation, window-tiled (R12, proven)
// ---------------------------------------------------------------------------
#define NPB 16
#define WROWS 48
__global__ __launch_bounds__(256) void local_kernel(const void* __restrict__ ei)
{
    __shared__ float rows[WROWS * Dn];
    __shared__ float alpha_s[NPB * DEG];
    __shared__ int   dloc[NPB * DEG];
    int tid = threadIdx.x, wid = tid >> 5, lane = tid & 31;
    int n0 = blockIdx.x * NPB;
    int w0 = (n0 + 1) & (Mn - 1);

    for (int i = tid; i < WROWS * (Dn / 4); i += 256) {
        int r = i >> 5, c4 = (i & 31) * 4;
        int gr = (w0 + r) & (Mn - 1);
        *(float4*)&rows[r * Dn + c4] = *(const float4*)&g_wg[gr * Dn + c4];
    }

    #pragma unroll
    for (int p = 0; p < 2; p++) {
        int nl = p * 8 + wid;
        int node = n0 + nl;
        long long e = (long long)node * DEG + lane;
        int dj;
        if (g_idx64) dj = (int)((const long long*)ei)[(long long)Mn * DEG + e];
        else         dj = ((const int*)ei)[(long long)Mn * DEG + e];
        dj &= (Mn - 1);
        dloc[nl * DEG + lane] = dj;
        float s = g_ssrc[node] + g_sdst[dj];
        s = (s > 0.f) ? s : 0.01f * s;
        float mx = s;
        #pragma unroll
        for (int off = 16; off; off >>= 1) mx = fmaxf(mx, __shfl_xor_sync(0xffffffffu, mx, off));
        float e2 = __expf(s - mx);
        float sum = e2;
        #pragma unroll
        for (int off = 16; off; off >>= 1) sum += __shfl_xor_sync(0xffffffffu, sum, off);
        alpha_s[nl * DEG + lane] = e2 / sum;
    }
    __syncthreads();

    int nl = tid >> 4;
    int d0 = (tid & 15) * 8;
    float acc[8] = {0.f, 0.f, 0.f, 0.f, 0.f, 0.f, 0.f, 0.f};
    #pragma unroll 4
    for (int j = 0; j < DEG; j++) {
        float a = alpha_s[nl * DEG + j];
        int dj = dloc[nl * DEG + j];
        unsigned u = (unsigned)((dj - w0) & (Mn - 1));
        const float* src = (u < WROWS) ? &rows[u * Dn + d0] : &g_wg[dj * Dn + d0];
        float4 v0 = *(const float4*)src;
        float4 v1 = *(const float4*)(src + 4);
        acc[0] += a * v0.x; acc[1] += a * v0.y; acc[2] += a * v0.z; acc[3] += a * v0.w;
        acc[4] += a * v1.x; acc[5] += a * v1.y; acc[6] += a * v1.z; acc[7] += a * v1.w;
    }
    float* dst = &g_local[(n0 + nl) * Dn + d0];
    *(float4*)dst       = make_float4(acc[0], acc[1], acc[2], acc[3]);
    *(float4*)(dst + 4) = make_float4(acc[4], acc[5], acc[6], acc[7]);
}

// ---------------------------------------------------------------------------
// flash attention: R12 config (BM=256, 1 CTA/SM, all fp32-acc, ldmatrix,
// triple buffer, one __syncthreads per iter). No fused epilogue.
// ---------------------------------------------------------------------------
__device__ __forceinline__ void load_tiles(uint32_t sbuf, int j0, int tid)
{
    #pragma unroll
    for (int l = 0; l < 4; l++) {
        int c = tid + 256 * l;
        int row = c >> 4, ch = c & 15;
        const char* s1 = (const char*)(g_kh + (size_t)(j0 + row) * Dn) + ch * 16;
        CP16(sbuf + row * 272 + ch * 16, s1);
    }
    #pragma unroll
    for (int l = 0; l < 4; l++) {
        int c = tid + 256 * l;
        int d = c >> 3, ch = c & 7;
        const char* s1 = (const char*)(g_cth + (size_t)d * Mn + j0) + ch * 16;
        CP16(sbuf + CTH_OFF + d * 144 + ch * 16, s1);
    }
}

__global__ __launch_bounds__(256, 1) void flash_mma_kernel()
{
    extern __shared__ char smem[];
    uint32_t sb = smem_to_u32(smem);
    int tid = threadIdx.x, wid = tid >> 5, lane = tid & 31;
    int mt = blockIdx.x >> 2, ks = blockIdx.x & 3;
    int m0 = mt * 256, jbase = ks * 2048;
    int rbase = m0 + wid * 32 + (lane >> 2);
    int kcol = (lane & 3) * 2;

    uint32_t kaddr = (uint32_t)((lane & 7) * 272 + (lane >> 3) * 16);
    uint32_t caddr = (uint32_t)(CTH_OFF + ((lane & 7) + (lane >> 4) * 8) * 144 + ((lane >> 3) & 1) * 16);

    uint32_t qf[2][8][4];
    #pragma unroll
    for (int mi = 0; mi < 2; mi++) {
        int r = rbase + mi * 16;
        #pragma unroll
        for (int g = 0; g < 8; g++) {
            int k0 = g * 16 + kcol;
            qf[mi][g][0] = *(const uint32_t*)&g_qh[r * Dn + k0];
            qf[mi][g][1] = *(const uint32_t*)&g_qh[(r + 8) * Dn + k0];
            qf[mi][g][2] = *(const uint32_t*)&g_qh[r * Dn + k0 + 8];
            qf[mi][g][3] = *(const uint32_t*)&g_qh[(r + 8) * Dn + k0 + 8];
        }
    }
    float kmax = __uint_as_float(g_kmaxenc);
    float ce[4];
    #pragma unroll
    for (int rr = 0; rr < 4; rr++)
        ce[rr] = 14.0f - g_qn[rbase + ((rr & 1) ? 8 : 0) + ((rr >> 1) ? 16 : 0)] * kmax * SC2;

    float Oa[2][16][4];
    #pragma unroll
    for (int mi = 0; mi < 2; mi++)
        #pragma unroll
        for (int f = 0; f < 16; f++)
            Oa[mi][f][0] = Oa[mi][f][1] = Oa[mi][f][2] = Oa[mi][f][3] = 0.f;
    __half2 hs[4];
    hs[0] = hs[1] = hs[2] = hs[3] = __floats2half2_rn(0.f, 0.f);
    float dn[4] = {0.f, 0.f, 0.f, 0.f};

    load_tiles(sb, jbase, tid);                  CP_COMMIT();
    load_tiles(sb + BUF_BYTES, jbase + 64, tid); CP_COMMIT();

    for (int it = 0; it < 32; it++) {
        CP_WAIT1();
        __syncthreads();
        if (it + 2 < 32) load_tiles(sb + ((it + 2) % 3) * BUF_BYTES, jbase + (it + 2) * 64, tid);
        CP_COMMIT();

        uint32_t kb = sb + (it % 3) * BUF_BYTES + kaddr;
        uint32_t cb = sb + (it % 3) * BUF_BYTES + caddr;

        #pragma unroll
        for (int gp = 0; gp < 4; gp++) {
            uint32_t Ah0[4], Ah1[4];
            #pragma unroll
            for (int tt = 0; tt < 2; tt++) {
                int t = gp * 2 + tt;
                float S0a[4] = {0.f, 0.f, 0.f, 0.f}, S0b[4] = {0.f, 0.f, 0.f, 0.f};
                float S1a[4] = {0.f, 0.f, 0.f, 0.f}, S1b[4] = {0.f, 0.f, 0.f, 0.f};
                #pragma unroll
                for (int g2 = 0; g2 < 8; g2 += 2) {
                    uint32_t r0, r1, r2, r3;
                    LDSM4(r0, r1, r2, r3, kb + t * 2176 + g2 * 32);
                    mma16816(S0a, qf[0][g2],     r0, r1);
                    mma16816(S1a, qf[1][g2],     r0, r1);
                    mma16816(S0b, qf[0][g2 + 1], r2, r3);
                    mma16816(S1b, qf[1][g2 + 1], r2, r3);
                }
                __half2 x01 = __floats2half2_rn(fmaf(S0a[0] + S0b[0], SC2, ce[0]),
                                                fmaf(S0a[1] + S0b[1], SC2, ce[0]));
                __half2 x23 = __floats2half2_rn(fmaf(S0a[2] + S0b[2], SC2, ce[1]),
                                                fmaf(S0a[3] + S0b[3], SC2, ce[1]));
                __half2 y01 = __floats2half2_rn(fmaf(S1a[0] + S1b[0], SC2, ce[2]),
                                                fmaf(S1a[1] + S1b[1], SC2, ce[2]));
                __half2 y23 = __floats2half2_rn(fmaf(S1a[2] + S1b[2], SC2, ce[3]),
                                                fmaf(S1a[3] + S1b[3], SC2, ce[3]));
                uint32_t e01 = h2ex2(*(uint32_t*)&x01);
                uint32_t e23 = h2ex2(*(uint32_t*)&x23);
                uint32_t f01 = h2ex2(*(uint32_t*)&y01);
                uint32_t f23 = h2ex2(*(uint32_t*)&y23);
                hs[0] = __hadd2(hs[0], *(__half2*)&e01);
                hs[1] = __hadd2(hs[1], *(__half2*)&e23);
                hs[2] = __hadd2(hs[2], *(__half2*)&f01);
                hs[3] = __hadd2(hs[3], *(__half2*)&f23);
                Ah0[tt * 2 + 0] = e01;
                Ah0[tt * 2 + 1] = e23;
                Ah1[tt * 2 + 0] = f01;
                Ah1[tt * 2 + 1] = f23;
            }
            #pragma unroll
            for (int f2 = 0; f2 < 8; f2++) {
                uint32_t r0, r1, r2, r3;
                LDSM4(r0, r1, r2, r3, cb + f2 * 2304 + gp * 32);
                mma16816(Oa[0][2 * f2],     Ah0, r0, r1);
                mma16816(Oa[1][2 * f2],     Ah1, r0, r1);
                mma16816(Oa[0][2 * f2 + 1], Ah0, r2, r3);
                mma16816(Oa[1][2 * f2 + 1], Ah1, r2, r3);
            }
        }
        #pragma unroll
        for (int rr = 0; rr < 4; rr++) {
            float2 f2 = __half22float2(hs[rr]);
            dn[rr] += f2.x + f2.y;
            hs[rr] = __floats2half2_rn(0.f, 0.f);
        }
    }

    #pragma unroll
    for (int rr = 0; rr < 4; rr++) {
        dn[rr] += __shfl_xor_sync(0xffffffffu, dn[rr], 1);
        dn[rr] += __shfl_xor_sync(0xffffffffu, dn[rr], 2);
    }
    if ((lane & 3) == 0) {
        g_den[ks][rbase]      = dn[0];
        g_den[ks][rbase + 8]  = dn[1];
        g_den[ks][rbase + 16] = dn[2];
        g_den[ks][rbase + 24] = dn[3];
    }

    float* Op = g_O[ks];
    #pragma unroll
    for (int mi = 0; mi < 2; mi++) {
        int r = rbase + mi * 16;
        #pragma unroll
        for (int f = 0; f < 16; f++) {
            int c0 = f * 8 + kcol;
            *(float2*)&Op[r * Dn + c0]       = make_float2(Oa[mi][f][0], Oa[mi][f][1]);
            *(float2*)&Op[(r + 8) * Dn + c0] = make_float2(Oa[mi][f][2], Oa[mi][f][3]);
        }
    }
}

// ---------------------------------------------------------------------------
// final: out = leaky_relu(local + sum(O_i)/sum(den_i) + z)
// ---------------------------------------------------------------------------
__global__ __launch_bounds__(256) void final_kernel(const float* __restrict__ z,
                                                    float* __restrict__ out)
{
    int i4 = blockIdx.x * 256 + threadIdx.x;
    int r = i4 >> 5;
    float inv = 1.0f / (g_den[0][r] + g_den[1][r] + g_den[2][r] + g_den[3][r]);
    float4 o0 = reinterpret_cast<const float4*>(g_O[0])[i4];
    float4 o1 = reinterpret_cast<const float4*>(g_O[1])[i4];
    float4 o2 = reinterpret_cast<const float4*>(g_O[2])[i4];
    float4 o3 = reinterpret_cast<const float4*>(g_O[3])[i4];
    float4 lc = reinterpret_cast<const float4*>(g_local)[i4];
    float4 zz = reinterpret_cast<const float4*>(z)[i4];
    float4 v;
    v.x = lc.x + (o0.x + o1.x + o2.x + o3.x) * inv + zz.x;
    v.y = lc.y + (o0.y + o1.y + o2.y + o3.y) * inv + zz.y;
    v.z = lc.z + (o0.z + o1.z + o2.z + o3.z) * inv + zz.z;
    v.w = lc.w + (o0.w + o1.w + o2.w + o3.w) * inv + zz.w;
    v.x = (v.x > 0.f) ? v.x : 0.01f * v.x;
    v.y = (v.y > 0.f) ? v.y : 0.01f * v.y;
    v.z = (v.z > 0.f) ? v.z : 0.01f * v.z;
    v.w = (v.w > 0.f) ? v.w : 0.01f * v.w;
    reinterpret_cast<float4*>(out)[i4] = v;
}

// ---------------------------------------------------------------------------
extern "C" void kernel_launch(void* const* d_in, const int* in_sizes, int n_in,
                              void* d_out, int out_size)
{
    const float* z  = (const float*)d_in[0];
    const void*  ei = d_in[1];
    const float* Wg = (const float*)d_in[2];
    const float* Wc = (const float*)d_in[3];
    const float* Wq = (const float*)d_in[4];
    const float* Wk = (const float*)d_in[5];
    const float* a  = (const float*)d_in[6];
    float* out = (float*)d_out;

    cudaFuncSetAttribute((const void*)flash_mma_kernel,
                         cudaFuncAttributeMaxDynamicSharedMemorySize, 3 * BUF_BYTES);
    cudaFuncSetAttribute((const void*)proj_mma_kernel,
                         cudaFuncAttributeMaxDynamicSharedMemorySize, 69632);

    convert_w_kernel<<<4, 256>>>(Wg, Wq, Wk, Wc);
    proj_mma_kernel<<<dim3(64, 4), 256, 69632>>>(z, a, (const int*)ei);
    local_kernel<<<Mn / NPB, 256>>>(ei);
    flash_mma_kernel<<<128, 256, 3 * BUF_BYTES>>>();
    final_kernel<<<1024, 256>>>(z, out);
}

// round 17
// speedup vs baseline: 1.1600x; 1.0224x over previous
#include <cuda_runtime.h>
#include <cuda_fp16.h>
#include <cuda_bf16.h>
#include <cstdint>

#define Mn 8192
#define Dn 128
#define DEG 32
#define SCALE 0.08838834764831845f
#define LOG2E 1.4426950408889634f
#define SC2   (SCALE * LOG2E)

// ---------------- device scratch (no allocations allowed) -------------------
__device__ float g_ssrc[Mn];
__device__ float g_sdst[Mn];
__device__ int   g_idx64;
__device__ __align__(16) float g_wg[Mn * Dn];
__device__ __align__(16) __half g_qh[Mn * Dn];     // [M, D]
__device__ __align__(16) __half g_kh[Mn * Dn];     // [M, D]
__device__ __align__(16) __half g_cth[Dn * Mn];    // [D, M] (transposed)
__device__ float g_qn[Mn];
__device__ unsigned int g_kmaxenc = 0;             // monotonic; idempotent across replays
__device__ __align__(16) float g_O[4][Mn * Dn];
__device__ float g_den[4][Mn];
__device__ __align__(16) char g_wplanes[4][69632]; // pre-converted W (smem image layout)

// ---------------- helpers ---------------------------------------------------
__device__ __forceinline__ uint32_t smem_to_u32(const void* p) {
    uint32_t a;
    asm("{ .reg .u64 t; cvta.to.shared.u64 t, %1; cvt.u32.u64 %0, t; }" : "=r"(a) : "l"(p));
    return a;
}
__device__ __forceinline__ void mma16816(float* d, const uint32_t* a, uint32_t b0, uint32_t b1) {
    asm volatile("mma.sync.aligned.m16n8k16.row.col.f32.f16.f16.f32 "
                 "{%0,%1,%2,%3}, {%4,%5,%6,%7}, {%8,%9}, {%0,%1,%2,%3};"
                 : "+f"(d[0]), "+f"(d[1]), "+f"(d[2]), "+f"(d[3])
                 : "r"(a[0]), "r"(a[1]), "r"(a[2]), "r"(a[3]), "r"(b0), "r"(b1));
}
__device__ __forceinline__ void mma16816h(uint32_t* d, const uint32_t* a, uint32_t b0, uint32_t b1) {
    asm volatile("mma.sync.aligned.m16n8k16.row.col.f16.f16.f16.f16 "
                 "{%0,%1}, {%2,%3,%4,%5}, {%6,%7}, {%0,%1};"
                 : "+r"(d[0]), "+r"(d[1])
                 : "r"(a[0]), "r"(a[1]), "r"(a[2]), "r"(a[3]), "r"(b0), "r"(b1));
}
__device__ __forceinline__ void mma16816bf(float* d, const uint32_t* a, uint32_t b0, uint32_t b1) {
    asm volatile("mma.sync.aligned.m16n8k16.row.col.f32.bf16.bf16.f32 "
                 "{%0,%1,%2,%3}, {%4,%5,%6,%7}, {%8,%9}, {%0,%1,%2,%3};"
                 : "+f"(d[0]), "+f"(d[1]), "+f"(d[2]), "+f"(d[3])
                 : "r"(a[0]), "r"(a[1]), "r"(a[2]), "r"(a[3]), "r"(b0), "r"(b1));
}
__device__ __forceinline__ uint32_t h2ex2(uint32_t x) {
    uint32_t r;
    asm("ex2.approx.f16x2 %0, %1;" : "=r"(r) : "r"(x));
    return r;
}
__device__ __forceinline__ uint32_t packbf2(float hi_x, float hi_y) {
    __nv_bfloat162 b = __floats2bfloat162_rn(hi_x, hi_y);
    return *(uint32_t*)&b;
}
#define LDSM4(r0, r1, r2, r3, addr) \
    asm volatile("ldmatrix.sync.aligned.m8n8.x4.shared.b16 {%0,%1,%2,%3}, [%4];" \
                 : "=r"(r0), "=r"(r1), "=r"(r2), "=r"(r3) : "r"(addr))
#define CP16(dst, src) asm volatile("cp.async.cg.shared.global [%0], [%1], 16;" :: "r"(dst), "l"(src))
#define CP_COMMIT() asm volatile("cp.async.commit_group;" ::: "memory")
#define CP_WAIT1()  asm volatile("cp.async.wait_group 1;"  ::: "memory")
#define CP_WAIT0()  asm volatile("cp.async.wait_group 0;"  ::: "memory")

#define CTH_OFF  17408
#define BUF_BYTES 35840

// ---------------------------------------------------------------------------
// W pre-conversion: fp32 -> split-bf16 planes in smem-image layout. grid 32.
// ---------------------------------------------------------------------------
__global__ __launch_bounds__(256) void convert_w_kernel(
    const float* __restrict__ Wg, const float* __restrict__ Wq,
    const float* __restrict__ Wk, const float* __restrict__ Wc)
{
    int b = blockIdx.x >> 3;
    int r0 = (blockIdx.x & 7) * 16;
    const float* W = (b == 0) ? Wg : (b == 1) ? Wq : (b == 2) ? Wk : Wc;
    char* dst = g_wplanes[b];
    for (int i = threadIdx.x; i < 16 * 64; i += 256) {
        int n = r0 + (i >> 6), k2 = (i & 63) * 2;
        float2 v = *(const float2*)&W[n * Dn + k2];
        float hx = __bfloat162float(__float2bfloat16(v.x));
        float hy = __bfloat162float(__float2bfloat16(v.y));
        *(uint32_t*)(dst + n * 272 + k2 * 2)         = packbf2(hx, hy);
        *(uint32_t*)(dst + 34816 + n * 272 + k2 * 2) = packbf2(v.x - hx, v.y - hy);
    }
}

// ---------------------------------------------------------------------------
// proj via tensor cores (split-bf16, 3 MMA). grid (64, 4). W by cp.async.
// Epilogue fuses: scores (which=0), qn (1), kmax (2), dtype detect.
// ---------------------------------------------------------------------------
__global__ __launch_bounds__(256, 1) void proj_mma_kernel(
    const float* __restrict__ z,
    const float* __restrict__ av, const int* __restrict__ ei32)
{
    extern __shared__ char smem[];             // 69632 B: Whi @0, Wlo @34816
    uint32_t sb = smem_to_u32(smem);
    int which = blockIdx.y;
    int m0 = blockIdx.x * 128;
    int tid = threadIdx.x, wid = tid >> 5, lane = tid & 31;

    {
        const char* src = g_wplanes[which];
        #pragma unroll
        for (int l = 0; l < 17; l++) {
            int off = (l * 256 + tid) * 16;
            CP16(sb + off, src + off);
        }
        CP_COMMIT();
    }

    if (which == 0 && blockIdx.x == 0 && tid == 0) {
        int s = 0;
        for (int k = 16; k < 48; k++) s |= ei32[2 * k + 1];
        g_idx64 = (s == 0) ? 1 : 0;
    }

    int rbase = m0 + wid * 16 + (lane >> 2);
    int kcol = (lane & 3) * 2;
    uint32_t ah[8][4], al[8][4];
    #pragma unroll
    for (int g = 0; g < 8; g++) {
        int k0 = g * 16 + kcol;
        #pragma unroll
        for (int q = 0; q < 4; q++) {
            int r = rbase + ((q & 1) ? 8 : 0);
            int kk = k0 + ((q >> 1) ? 8 : 0);
            float2 v = *(const float2*)&z[r * Dn + kk];
            float hx = __bfloat162float(__float2bfloat16(v.x));
            float hy = __bfloat162float(__float2bfloat16(v.y));
            ah[g][q] = packbf2(hx, hy);
            al[g][q] = packbf2(v.x - hx, v.y - hy);
        }
    }
    CP_WAIT0();
    __syncthreads();

    float acc[16][4];
    #pragma unroll
    for (int f = 0; f < 16; f++) acc[f][0] = acc[f][1] = acc[f][2] = acc[f][3] = 0.f;

    int boff = (lane >> 2) * 272 + kcol * 2;
    #pragma unroll
    for (int g = 0; g < 8; g++) {
        #pragma unroll
        for (int f = 0; f < 16; f++) {
            const char* p = smem + boff + f * 2176 + g * 32;
            uint32_t bh0 = *(const uint32_t*)p;
            uint32_t bh1 = *(const uint32_t*)(p + 16);
            uint32_t bl0 = *(const uint32_t*)(p + 34816);
            uint32_t bl1 = *(const uint32_t*)(p + 34816 + 16);
            mma16816bf(acc[f], ah[g], bh0, bh1);
            mma16816bf(acc[f], ah[g], bl0, bl1);
            mma16816bf(acc[f], al[g], bh0, bh1);
        }
    }

    #pragma unroll
    for (int f = 0; f < 16; f++) {
        int c0 = f * 8 + kcol;
        int r = rbase;
        if (which == 0) {
            *(float2*)&g_wg[r * Dn + c0]       = make_float2(acc[f][0], acc[f][1]);
            *(float2*)&g_wg[(r + 8) * Dn + c0] = make_float2(acc[f][2], acc[f][3]);
        } else if (which == 1) {
            *(__half2*)&g_qh[r * Dn + c0]       = __floats2half2_rn(acc[f][0], acc[f][1]);
            *(__half2*)&g_qh[(r + 8) * Dn + c0] = __floats2half2_rn(acc[f][2], acc[f][3]);
        } else if (which == 2) {
            *(__half2*)&g_kh[r * Dn + c0]       = __floats2half2_rn(acc[f][0], acc[f][1]);
            *(__half2*)&g_kh[(r + 8) * Dn + c0] = __floats2half2_rn(acc[f][2], acc[f][3]);
        } else {
            g_cth[(size_t)c0 * Mn + r]           = __float2half(acc[f][0]);
            g_cth[(size_t)(c0 + 1) * Mn + r]     = __float2half(acc[f][1]);
            g_cth[(size_t)c0 * Mn + r + 8]       = __float2half(acc[f][2]);
            g_cth[(size_t)(c0 + 1) * Mn + r + 8] = __float2half(acc[f][3]);
        }
    }

    if (which == 0) {
        float s0a = 0.f, s1a = 0.f, s0b = 0.f, s1b = 0.f;
        #pragma unroll
        for (int f = 0; f < 16; f++) {
            int c0 = f * 8 + kcol;
            s0a += acc[f][0] * av[c0] + acc[f][1] * av[c0 + 1];
            s1a += acc[f][0] * av[c0 + Dn] + acc[f][1] * av[c0 + Dn + 1];
            s0b += acc[f][2] * av[c0] + acc[f][3] * av[c0 + 1];
            s1b += acc[f][2] * av[c0 + Dn] + acc[f][3] * av[c0 + Dn + 1];
        }
        #pragma unroll
        for (int off = 1; off <= 2; off <<= 1) {
            s0a += __shfl_xor_sync(0xffffffffu, s0a, off);
            s1a += __shfl_xor_sync(0xffffffffu, s1a, off);
            s0b += __shfl_xor_sync(0xffffffffu, s0b, off);
            s1b += __shfl_xor_sync(0xffffffffu, s1b, off);
        }
        if ((lane & 3) == 0) {
            g_ssrc[rbase] = s0a;     g_sdst[rbase] = s1a;
            g_ssrc[rbase + 8] = s0b; g_sdst[rbase + 8] = s1b;
        }
    } else if (which == 1 || which == 2) {
        float na = 0.f, nb = 0.f;   // norms of the ROUNDED fp16 values
        #pragma unroll
        for (int f = 0; f < 16; f++) {
            #pragma unroll
            for (int q = 0; q < 4; q++) {
                float h = __half2float(__float2half_rn(acc[f][q]));
                if (q < 2) na += h * h; else nb += h * h;
            }
        }
        #pragma unroll
        for (int off = 1; off <= 2; off <<= 1) {
            na += __shfl_xor_sync(0xffffffffu, na, off);
            nb += __shfl_xor_sync(0xffffffffu, nb, off);
        }
        if ((lane & 3) == 0) {
            float ra = sqrtf(na), rb = sqrtf(nb);
            if (which == 1) {
                g_qn[rbase] = ra;
                g_qn[rbase + 8] = rb;
            } else {
                atomicMax(&g_kmaxenc, __float_as_uint(fmaxf(ra, rb)));
            }
        }
    }
}

// ---------------------------------------------------------------------------
// flash attention: BM=256, fp32-acc S software-pipelined one gp ahead,
// fp16-acc O (prescale 2^12), ldmatrix, triple buffer, 1 sync/iter.
// ---------------------------------------------------------------------------
__device__ __forceinline__ void load_tiles(uint32_t sbuf, int j0, int tid)
{
    #pragma unroll
    for (int l = 0; l < 4; l++) {
        int c = tid + 256 * l;
        int row = c >> 4, ch = c & 15;
        const char* s1 = (const char*)(g_kh + (size_t)(j0 + row) * Dn) + ch * 16;
        CP16(sbuf + row * 272 + ch * 16, s1);
    }
    #pragma unroll
    for (int l = 0; l < 4; l++) {
        int c = tid + 256 * l;
        int d = c >> 3, ch = c & 7;
        const char* s1 = (const char*)(g_cth + (size_t)d * Mn + j0) + ch * 16;
        CP16(sbuf + CTH_OFF + d * 144 + ch * 16, s1);
    }
}

// compute all S for one gp (2 tt) into Sb[set][32]
#define CSET(set, gp_) do {                                                    \
    _Pragma("unroll")                                                          \
    for (int tt = 0; tt < 2; tt++) {                                           \
        int t_ = (gp_) * 2 + tt;                                               \
        _Pragma("unroll")                                                      \
        for (int i_ = 0; i_ < 16; i_++) Sb[set][tt * 16 + i_] = 0.f;           \
        _Pragma("unroll")                                                      \
        for (int g2 = 0; g2 < 8; g2 += 2) {                                    \
            uint32_t r0, r1, r2, r3;                                           \
            LDSM4(r0, r1, r2, r3, kb + t_ * 2176 + g2 * 32);                   \
            mma16816(&Sb[set][tt * 16 + 0],  qf[0][g2],     r0, r1);           \
            mma16816(&Sb[set][tt * 16 + 4],  qf[1][g2],     r0, r1);           \
            mma16816(&Sb[set][tt * 16 + 8],  qf[0][g2 + 1], r2, r3);           \
            mma16816(&Sb[set][tt * 16 + 12], qf[1][g2 + 1], r2, r3);           \
        }                                                                      \
    }                                                                          \
} while (0)

__global__ __launch_bounds__(256, 1) void flash_mma_kernel()
{
    extern __shared__ char smem[];
    uint32_t sb = smem_to_u32(smem);
    int tid = threadIdx.x, wid = tid >> 5, lane = tid & 31;
    int mt = blockIdx.x >> 2, ks = blockIdx.x & 3;
    int m0 = mt * 256, jbase = ks * 2048;
    int rbase = m0 + wid * 32 + (lane >> 2);
    int kcol = (lane & 3) * 2;

    uint32_t kaddr = (uint32_t)((lane & 7) * 272 + (lane >> 3) * 16);
    uint32_t caddr = (uint32_t)(CTH_OFF + ((lane & 7) + (lane >> 4) * 8) * 144 + ((lane >> 3) & 1) * 16);

    uint32_t qf[2][8][4];
    #pragma unroll
    for (int mi = 0; mi < 2; mi++) {
        int r = rbase + mi * 16;
        #pragma unroll
        for (int g = 0; g < 8; g++) {
            int k0 = g * 16 + kcol;
            qf[mi][g][0] = *(const uint32_t*)&g_qh[r * Dn + k0];
            qf[mi][g][1] = *(const uint32_t*)&g_qh[(r + 8) * Dn + k0];
            qf[mi][g][2] = *(const uint32_t*)&g_qh[r * Dn + k0 + 8];
            qf[mi][g][3] = *(const uint32_t*)&g_qh[(r + 8) * Dn + k0 + 8];
        }
    }
    float kmax = __uint_as_float(g_kmaxenc);
    float ce[4];
    #pragma unroll
    for (int rr = 0; rr < 4; rr++)
        ce[rr] = 12.0f - g_qn[rbase + ((rr & 1) ? 8 : 0) + ((rr >> 1) ? 16 : 0)] * kmax * SC2;

    uint32_t Oh[2][16][2];              // fp16x2 accumulators
    #pragma unroll
    for (int mi = 0; mi < 2; mi++)
        #pragma unroll
        for (int f = 0; f < 16; f++)
            Oh[mi][f][0] = Oh[mi][f][1] = 0u;
    __half2 hs[4];
    hs[0] = hs[1] = hs[2] = hs[3] = __floats2half2_rn(0.f, 0.f);
    float dn[4] = {0.f, 0.f, 0.f, 0.f};

    load_tiles(sb, jbase, tid);                  CP_COMMIT();
    load_tiles(sb + BUF_BYTES, jbase + 64, tid); CP_COMMIT();

    for (int it = 0; it < 32; it++) {
        CP_WAIT1();
        __syncthreads();
        if (it + 2 < 32) load_tiles(sb + ((it + 2) % 3) * BUF_BYTES, jbase + (it + 2) * 64, tid);
        CP_COMMIT();

        uint32_t kb = sb + (it % 3) * BUF_BYTES + kaddr;
        uint32_t cb = sb + (it % 3) * BUF_BYTES + caddr;

        float Sb[2][32];
        CSET(0, 0);
        #pragma unroll
        for (int gp = 0; gp < 4; gp++) {
            int cur = gp & 1;
            if (gp < 3) {                         // issue next gp's S before exp
                if (cur == 0) CSET(1, gp + 1);
                else          CSET(0, gp + 1);
            }
            uint32_t Ah0[4], Ah1[4];
            #pragma unroll
            for (int tt = 0; tt < 2; tt++) {
                __half2 x01 = __floats2half2_rn(
                    fmaf(Sb[cur][tt*16+0] + Sb[cur][tt*16+8],  SC2, ce[0]),
                    fmaf(Sb[cur][tt*16+1] + Sb[cur][tt*16+9],  SC2, ce[0]));
                __half2 x23 = __floats2half2_rn(
                    fmaf(Sb[cur][tt*16+2] + Sb[cur][tt*16+10], SC2, ce[1]),
                    fmaf(Sb[cur][tt*16+3] + Sb[cur][tt*16+11], SC2, ce[1]));
                __half2 y01 = __floats2half2_rn(
                    fmaf(Sb[cur][tt*16+4] + Sb[cur][tt*16+12], SC2, ce[2]),
                    fmaf(Sb[cur][tt*16+5] + Sb[cur][tt*16+13], SC2, ce[2]));
                __half2 y23 = __floats2half2_rn(
                    fmaf(Sb[cur][tt*16+6] + Sb[cur][tt*16+14], SC2, ce[3]),
                    fmaf(Sb[cur][tt*16+7] + Sb[cur][tt*16+15], SC2, ce[3]));
                uint32_t e01 = h2ex2(*(uint32_t*)&x01);
                uint32_t e23 = h2ex2(*(uint32_t*)&x23);
                uint32_t f01 = h2ex2(*(uint32_t*)&y01);
                uint32_t f23 = h2ex2(*(uint32_t*)&y23);
                hs[0] = __hadd2(hs[0], *(__half2*)&e01);
                hs[1] = __hadd2(hs[1], *(__half2*)&e23);
                hs[2] = __hadd2(hs[2], *(__half2*)&f01);
                hs[3] = __hadd2(hs[3], *(__half2*)&f23);
                Ah0[tt * 2 + 0] = e01;
                Ah0[tt * 2 + 1] = e23;
                Ah1[tt * 2 + 0] = f01;
                Ah1[tt * 2 + 1] = f23;
            }
            #pragma unroll
            for (int f2 = 0; f2 < 8; f2++) {
                uint32_t r0, r1, r2, r3;
                LDSM4(r0, r1, r2, r3, cb + f2 * 2304 + gp * 32);
                mma16816h(Oh[0][2 * f2],     Ah0, r0, r1);
                mma16816h(Oh[1][2 * f2],     Ah1, r0, r1);
                mma16816h(Oh[0][2 * f2 + 1], Ah0, r2, r3);
                mma16816h(Oh[1][2 * f2 + 1], Ah1, r2, r3);
            }
        }
        #pragma unroll
        for (int rr = 0; rr < 4; rr++) {
            float2 f2 = __half22float2(hs[rr]);
            dn[rr] += f2.x + f2.y;
            hs[rr] = __floats2half2_rn(0.f, 0.f);
        }
    }

    #pragma unroll
    for (int rr = 0; rr < 4; rr++) {
        dn[rr] += __shfl_xor_sync(0xffffffffu, dn[rr], 1);
        dn[rr] += __shfl_xor_sync(0xffffffffu, dn[rr], 2);
    }
    if ((lane & 3) == 0) {
        g_den[ks][rbase]      = dn[0];
        g_den[ks][rbase + 8]  = dn[1];
        g_den[ks][rbase + 16] = dn[2];
        g_den[ks][rbase + 24] = dn[3];
    }

    float* Op = g_O[ks];
    #pragma unroll
    for (int mi = 0; mi < 2; mi++) {
        int r = rbase + mi * 16;
        #pragma unroll
        for (int f = 0; f < 16; f++) {
            int c0 = f * 8 + kcol;
            float2 v0 = __half22float2(*(__half2*)&Oh[mi][f][0]);
            float2 v1 = __half22float2(*(__half2*)&Oh[mi][f][1]);
            *(float2*)&Op[r * Dn + c0]       = v0;
            *(float2*)&Op[(r + 8) * Dn + c0] = v1;
        }
    }
}

// ---------------------------------------------------------------------------
// fused local aggregation + final epilogue (runs after flash):
// out = leaky_relu(local + sum(O_i)/sum(den_i) + z). 512 blocks x 16 nodes.
// ---------------------------------------------------------------------------
#define NPB 16
#define WROWS 48
__global__ __launch_bounds__(256) void local_final_kernel(const void* __restrict__ ei,
                                                          const float* __restrict__ z,
                                                          float* __restrict__ out)
{
    __shared__ float rows[WROWS * Dn];
    __shared__ float alpha_s[NPB * DEG];
    __shared__ int   dloc[NPB * DEG];
    int tid = threadIdx.x, wid = tid >> 5, lane = tid & 31;
    int n0 = blockIdx.x * NPB;
    int w0 = (n0 + 1) & (Mn - 1);

    for (int i = tid; i < WROWS * (Dn / 4); i += 256) {
        int r = i >> 5, c4 = (i & 31) * 4;
        int gr = (w0 + r) & (Mn - 1);
        *(float4*)&rows[r * Dn + c4] = *(const float4*)&g_wg[gr * Dn + c4];
    }

    #pragma unroll
    for (int p = 0; p < 2; p++) {
        int nl = p * 8 + wid;
        int node = n0 + nl;
        long long e = (long long)node * DEG + lane;
        int dj;
        if (g_idx64) dj = (int)((const long long*)ei)[(long long)Mn * DEG + e];
        else         dj = ((const int*)ei)[(long long)Mn * DEG + e];
        dj &= (Mn - 1);
        dloc[nl * DEG + lane] = dj;
        float s = g_ssrc[node] + g_sdst[dj];
        s = (s > 0.f) ? s : 0.01f * s;
        float mx = s;
        #pragma unroll
        for (int off = 16; off; off >>= 1) mx = fmaxf(mx, __shfl_xor_sync(0xffffffffu, mx, off));
        float e2 = __expf(s - mx);
        float sum = e2;
        #pragma unroll
        for (int off = 16; off; off >>= 1) sum += __shfl_xor_sync(0xffffffffu, sum, off);
        alpha_s[nl * DEG + lane] = e2 / sum;
    }
    __syncthreads();

    int nl = tid >> 4;
    int d0 = (tid & 15) * 8;
    float acc[8] = {0.f, 0.f, 0.f, 0.f, 0.f, 0.f, 0.f, 0.f};
    #pragma unroll 4
    for (int j = 0; j < DEG; j++) {
        float a = alpha_s[nl * DEG + j];
        int dj = dloc[nl * DEG + j];
        unsigned u = (unsigned)((dj - w0) & (Mn - 1));
        const float* src = (u < WROWS) ? &rows[u * Dn + d0] : &g_wg[dj * Dn + d0];
        float4 v0 = *(const float4*)src;
        float4 v1 = *(const float4*)(src + 4);
        acc[0] += a * v0.x; acc[1] += a * v0.y; acc[2] += a * v0.z; acc[3] += a * v0.w;
        acc[4] += a * v1.x; acc[5] += a * v1.y; acc[6] += a * v1.z; acc[7] += a * v1.w;
    }

    int node = n0 + nl;
    float inv = 1.0f / (g_den[0][node] + g_den[1][node] + g_den[2][node] + g_den[3][node]);
    #pragma unroll
    for (int h = 0; h < 2; h++) {
        size_t o = (size_t)node * Dn + d0 + h * 4;
        float4 s = make_float4(0.f, 0.f, 0.f, 0.f);
        #pragma unroll
        for (int k2 = 0; k2 < 4; k2++) {       // fixed order: deterministic
            float4 t = *(const float4*)&g_O[k2][o];
            s.x += t.x; s.y += t.y; s.z += t.z; s.w += t.w;
        }
        float4 zz = *(const float4*)&z[o];
        float4 v;
        v.x = acc[h * 4 + 0] + s.x * inv + zz.x;
        v.y = acc[h * 4 + 1] + s.y * inv + zz.y;
        v.z = acc[h * 4 + 2] + s.z * inv + zz.z;
        v.w = acc[h * 4 + 3] + s.w * inv + zz.w;
        v.x = (v.x > 0.f) ? v.x : 0.01f * v.x;
        v.y = (v.y > 0.f) ? v.y : 0.01f * v.y;
        v.z = (v.z > 0.f) ? v.z : 0.01f * v.z;
        v.w = (v.w > 0.f) ? v.w : 0.01f * v.w;
        *(float4*)&out[o] = v;
    }
}

// ---------------------------------------------------------------------------
extern "C" void kernel_launch(void* const* d_in, const int* in_sizes, int n_in,
                              void* d_out, int out_size)
{
    const float* z  = (const float*)d_in[0];
    const void*  ei = d_in[1];
    const float* Wg = (const float*)d_in[2];
    const float* Wc = (const float*)d_in[3];
    const float* Wq = (const float*)d_in[4];
    const float* Wk = (const float*)d_in[5];
    const float* a  = (const float*)d_in[6];
    float* out = (float*)d_out;

    cudaFuncSetAttribute((const void*)flash_mma_kernel,
                         cudaFuncAttributeMaxDynamicSharedMemorySize, 3 * BUF_BYTES);
    cudaFuncSetAttribute((const void*)proj_mma_kernel,
                         cudaFuncAttributeMaxDynamicSharedMemorySize, 69632);

    convert_w_kernel<<<32, 256>>>(Wg, Wq, Wk, Wc);
    proj_mma_kernel<<<dim3(64, 4), 256, 69632>>>(z, a, (const int*)ei);
    flash_mma_kernel<<<128, 256, 3 * BUF_BYTES>>>();
    local_final_kernel<<<Mn / NPB, 256>>>(ei, z, out);
}